// round 15
// baseline (speedup 1.0000x reference)
#include <cuda_runtime.h>
#include <cuda_fp16.h>
#include <cstdint>

#define T_TOKENS 4096
#define DDIM 1024
#define MDIM 2048
#define NEXP 8
#define ROWS_PAD 9216      // 72 tiles * 128 rows
#define MAX_TILES 72

// Block layout: all GEMM operands stored as 16KB blocks of (64 k) x (128 n/m),
// A blocks: 128 m x 64 k, element (m,k) at byte m*128 + ((k*2) ^ ((m&7)<<4))
// B blocks: 64 k x 128 n, element (k,n) at byte k*256 + ((n*2) ^ ((k&7)<<4))
__device__ __half g_Wg[NEXP * DDIM * MDIM];
__device__ __half g_Wu[NEXP * DDIM * MDIM];
__device__ __half g_Wo[NEXP * MDIM * DDIM];
__device__ __half g_X[ROWS_PAD * DDIM];
__device__ __half g_H[ROWS_PAD * MDIM];
__device__ float  g_Y[ROWS_PAD * DDIM];
__device__ int    g_counts[NEXP];
__device__ int    g_offsets[NEXP + 1];
__device__ int    g_tile_expert[MAX_TILES];
__device__ int    g_tok_e[T_TOKENS * 2];
__device__ int    g_tok_slot[T_TOKENS * 2];
__device__ float  g_tok_w[T_TOKENS * 2];

// ---------------- helpers ----------------
__device__ __forceinline__ uint32_t smem_u32(const void* p) {
    uint32_t a;
    asm("{ .reg .u64 t; cvta.to.shared.u64 t, %1; cvt.u32.u64 %0, t; }" : "=r"(a) : "l"(p));
    return a;
}
__device__ __forceinline__ void mbar_init(uint32_t a, uint32_t cnt) {
    asm volatile("mbarrier.init.shared.b64 [%0], %1;" :: "r"(a), "r"(cnt) : "memory");
}
__device__ __forceinline__ void mbar_arrive(uint32_t a) {
    asm volatile("mbarrier.arrive.shared.b64 _, [%0];" :: "r"(a) : "memory");
}
__device__ __forceinline__ void mbar_expect_tx(uint32_t a, uint32_t bytes) {
    asm volatile("mbarrier.arrive.expect_tx.shared.b64 _, [%0], %1;" :: "r"(a), "r"(bytes) : "memory");
}
__device__ __forceinline__ void bulk_g2s(uint32_t dst, const void* src, uint32_t bytes, uint32_t mbar) {
    asm volatile("cp.async.bulk.shared::cta.global.mbarrier::complete_tx::bytes [%0], [%1], %2, [%3];"
                 :: "r"(dst), "l"(src), "r"(bytes), "r"(mbar) : "memory");
}
__device__ __forceinline__ void mbar_wait(uint32_t a, uint32_t parity) {
    asm volatile(
        "{\n\t.reg .pred P1;\n\t"
        "W%=:\n\t"
        "mbarrier.try_wait.parity.acquire.cta.shared::cta.b64 P1, [%0], %1, 0x989680;\n\t"
        "@P1 bra.uni D%=;\n\t"
        "bra.uni W%=;\n\t"
        "D%=:\n\t}"
        :: "r"(a), "r"(parity) : "memory");
}
#define FENCE_ASYNC() asm volatile("fence.proxy.async.shared::cta;" ::: "memory")
__device__ __forceinline__ void ldm_x4(uint32_t* r, uint32_t addr) {
    asm volatile("ldmatrix.sync.aligned.m8n8.x4.shared.b16 {%0,%1,%2,%3}, [%4];"
                 : "=r"(r[0]), "=r"(r[1]), "=r"(r[2]), "=r"(r[3]) : "r"(addr));
}
__device__ __forceinline__ void ldm_x4_t(uint32_t* r, uint32_t addr) {
    asm volatile("ldmatrix.sync.aligned.m8n8.x4.trans.shared.b16 {%0,%1,%2,%3}, [%4];"
                 : "=r"(r[0]), "=r"(r[1]), "=r"(r[2]), "=r"(r[3]) : "r"(addr));
}
__device__ __forceinline__ void mma16816(float* c, const uint32_t* a, const uint32_t* b) {
    asm volatile(
        "mma.sync.aligned.m16n8k16.row.col.f32.f16.f16.f32 "
        "{%0,%1,%2,%3}, {%4,%5,%6,%7}, {%8,%9}, {%0,%1,%2,%3};"
        : "+f"(c[0]), "+f"(c[1]), "+f"(c[2]), "+f"(c[3])
        : "r"(a[0]), "r"(a[1]), "r"(a[2]), "r"(a[3]), "r"(b[0]), "r"(b[1]));
}

// ---------------- launch 1: convert all weights + zero counts + zero X ----------------
__device__ __forceinline__ void convert_body(const float* __restrict__ src,
                                             __half* __restrict__ dst,
                                             int KD, int ND, int x) {
    __shared__ float tile[64][128];
    int NT = ND / 128, KT = KD / 64;
    int e = x / (NT * KT);
    int nt = (x / KT) % NT;
    int kt = x % KT;
    int k0 = kt * 64, n0 = nt * 128;
    int tid = threadIdx.x;              // 256
    const float* s = src + (size_t)e * KD * ND;
    #pragma unroll
    for (int i = 0; i < 8; i++) {
        int idx = tid + i * 256;        // 2048 float4
        int k = idx >> 5, nq = (idx & 31) * 4;
        float4 v = *reinterpret_cast<const float4*>(s + (size_t)(k0 + k) * ND + n0 + nq);
        *reinterpret_cast<float4*>(&tile[k][nq]) = v;
    }
    __syncthreads();
    uint4* out = reinterpret_cast<uint4*>(dst + (size_t)x * 8192);
    #pragma unroll
    for (int i = 0; i < 4; i++) {
        int idx = tid + i * 256;        // 1024 uint4
        int k = idx >> 4;
        int wb = (idx & 15) * 16;
        int n = (wb ^ ((k & 7) << 4)) >> 1;
        float4 v0 = *reinterpret_cast<const float4*>(&tile[k][n]);
        float4 v1 = *reinterpret_cast<const float4*>(&tile[k][n + 4]);
        __half2 h[4];
        h[0] = __floats2half2_rn(v0.x, v0.y);
        h[1] = __floats2half2_rn(v0.z, v0.w);
        h[2] = __floats2half2_rn(v1.x, v1.y);
        h[3] = __floats2half2_rn(v1.z, v1.w);
        out[idx] = *reinterpret_cast<uint4*>(h);
    }
}

__global__ void convert_kernel(const float* __restrict__ wg,
                               const float* __restrict__ wu,
                               const float* __restrict__ wo) {
    int flat = (blockIdx.y * gridDim.x + blockIdx.x) * blockDim.x + threadIdx.x;
    if (flat < NEXP) g_counts[flat] = 0;
    const int nx = ROWS_PAD * DDIM / 8;
    if (flat < nx) reinterpret_cast<uint4*>(g_X)[flat] = make_uint4(0, 0, 0, 0);

    if (blockIdx.y == 0)      convert_body(wg, g_Wg, DDIM, MDIM, blockIdx.x);
    else if (blockIdx.y == 1) convert_body(wu, g_Wu, DDIM, MDIM, blockIdx.x);
    else                      convert_body(wo, g_Wo, MDIM, DDIM, blockIdx.x);
}

// ---------------- launch 2: router ----------------
#define RT_TPB 16
__global__ void __launch_bounds__(256) router_kernel(const float* __restrict__ residual,
                                                     const float* __restrict__ Wr) {
    __shared__ float wrT[NEXP][DDIM];
    __shared__ float xs[DDIM];
    __shared__ float logits[NEXP];
    int tid = threadIdx.x, w = tid >> 5, lane = tid & 31;
    #pragma unroll
    for (int i = 0; i < 32; i++) {
        int idx = tid + i * 256;
        wrT[idx & 7][idx >> 3] = Wr[idx];
    }
    __syncthreads();
    const float4* wr4 = reinterpret_cast<const float4*>(&wrT[w][0]);
    for (int tt = 0; tt < RT_TPB; tt++) {
        int t = blockIdx.x * RT_TPB + tt;
        reinterpret_cast<float4*>(xs)[tid] =
            reinterpret_cast<const float4*>(residual + (size_t)t * DDIM)[tid];
        __syncthreads();
        const float4* xs4 = reinterpret_cast<const float4*>(xs);
        float s = 0.f;
        #pragma unroll
        for (int j = 0; j < 8; j++) {
            float4 xv = xs4[j * 32 + lane];
            float4 wv = wr4[j * 32 + lane];
            s += xv.x * wv.x + xv.y * wv.y + xv.z * wv.z + xv.w * wv.w;
        }
        #pragma unroll
        for (int o = 16; o > 0; o >>= 1) s += __shfl_xor_sync(0xffffffff, s, o);
        if (lane == 0) logits[w] = s;
        __syncthreads();
        if (tid == 0) {
            float mx = logits[0];
            #pragma unroll
            for (int e = 1; e < NEXP; e++) mx = fmaxf(mx, logits[e]);
            float p[NEXP]; float sum = 0.f;
            #pragma unroll
            for (int e = 0; e < NEXP; e++) { p[e] = expf(logits[e] - mx); sum += p[e]; }
            #pragma unroll
            for (int e = 0; e < NEXP; e++) p[e] /= sum;
            int i1 = 0;
            #pragma unroll
            for (int e = 1; e < NEXP; e++) if (p[e] > p[i1]) i1 = e;
            int i2 = -1;
            #pragma unroll
            for (int e = 0; e < NEXP; e++) {
                if (e == i1) continue;
                if (i2 < 0 || p[e] > p[i2]) i2 = e;
            }
            float w1 = p[i1], w2 = p[i2];
            float inv = 1.f / (w1 + w2 + 1e-8f);
            w1 *= inv; w2 *= inv;
            int s1 = atomicAdd(&g_counts[i1], 1);
            int s2 = atomicAdd(&g_counts[i2], 1);
            g_tok_e[2 * t] = i1;     g_tok_e[2 * t + 1] = i2;
            g_tok_slot[2 * t] = s1;  g_tok_slot[2 * t + 1] = s2;
            g_tok_w[2 * t] = w1;     g_tok_w[2 * t + 1] = w2;
        }
        __syncthreads();
    }
}

// ---------------- launch 3: fused scatter+gather ----------------
__global__ void sg_kernel(const float* __restrict__ residual) {
    int i = blockIdx.x;
    int tid = threadIdx.x;
    if (i == 0 && tid == 0) {
        int off = 0, tile = 0;
        #pragma unroll
        for (int e = 0; e < NEXP; e++) {
            g_offsets[e] = off;
            int nt = (g_counts[e] + 127) >> 7;
            for (int k = 0; k < nt; k++) g_tile_expert[tile++] = e;
            off += nt << 7;
        }
        g_offsets[NEXP] = off;
        for (; tile < MAX_TILES; tile++) g_tile_expert[tile] = -1;
    }
    int e = g_tok_e[i];
    int off = 0;
    #pragma unroll
    for (int q = 0; q < NEXP; q++)
        if (q < e) off += ((g_counts[q] + 127) >> 7) << 7;
    int row = off + g_tok_slot[i];
    int tok = i >> 1;
    int c = tid * 8;
    const float4* src = reinterpret_cast<const float4*>(residual + (size_t)tok * DDIM + c);
    float4 a = src[0], b = src[1];
    __half2 h[4];
    h[0] = __floats2half2_rn(a.x, a.y); h[1] = __floats2half2_rn(a.z, a.w);
    h[2] = __floats2half2_rn(b.x, b.y); h[3] = __floats2half2_rn(b.z, b.w);
    int rt = row >> 7, m = row & 127;
    int kt = c >> 6, k = c & 63;
    reinterpret_cast<uint4*>(g_X)[(size_t)(rt * 16 + kt) * 1024 + m * 8 + ((k >> 3) ^ (m & 7))] =
        *reinterpret_cast<uint4*>(h);
}

// ================= launch 4 (PROFILED): GEMM1, 256 threads, 2x4 warps of 64x32, 4-stage =================
// SMEM: [0..32) full mbars, [64..96) empty mbars, [1024..) 4 stages of 48KB
#define G1_STG 4
#define G1_NC 16
#define G1_STAGE_B 49152
#define G1_SMEM (1024 + G1_STG * G1_STAGE_B)
#define G1_WARPS 8

__global__ void __launch_bounds__(256, 1) gemm1_kernel(const float* __restrict__ bg,
                                                       const float* __restrict__ bu) {
    int e = g_tile_expert[blockIdx.y];
    if (e < 0) return;
    int rt = blockIdx.y, nt_ = blockIdx.x;
    int row0 = rt * 128, n0 = nt_ * 128;
    extern __shared__ char smc[];
    uint32_t sb = smem_u32(smc);
    int tid = threadIdx.x, lane = tid & 31, w = tid >> 5;
    int wm = w >> 2, wn = w & 3;        // 2x4 warps, 64x32 each

    const char* Ablk  = (const char*)g_X  + (size_t)(rt * 16) * 16384;
    const char* Bgblk = (const char*)g_Wg + (size_t)((e * 16 + nt_) * 16) * 16384;
    const char* Bublk = (const char*)g_Wu + (size_t)((e * 16 + nt_) * 16) * 16384;

    if (tid == 0) {
        #pragma unroll
        for (int s = 0; s < G1_STG; s++) {
            mbar_init(sb + 8 * s, 1);                 // full
            mbar_init(sb + 64 + 8 * s, G1_WARPS);     // empty (one arrive per warp)
        }
    }
    __syncthreads();
    FENCE_ASYNC();

    auto issue = [&](int c) {
        int b = c % G1_STG;
        uint32_t mb = sb + 8 * b;
        uint32_t dst = sb + 1024 + b * G1_STAGE_B;
        mbar_expect_tx(mb, G1_STAGE_B);
        bulk_g2s(dst,          Ablk  + (size_t)c * 16384, 16384, mb);
        bulk_g2s(dst + 16384,  Bgblk + (size_t)c * 16384, 16384, mb);
        bulk_g2s(dst + 32768,  Bublk + (size_t)c * 16384, 16384, mb);
    };
    if (tid == 0) { issue(0); issue(1); issue(2); issue(3); }

    float accG[4][4][4], accU[4][4][4];
    #pragma unroll
    for (int mt = 0; mt < 4; mt++)
        #pragma unroll
        for (int nt = 0; nt < 4; nt++)
            #pragma unroll
            for (int q = 0; q < 4; q++) { accG[mt][nt][q] = 0.f; accU[mt][nt][q] = 0.f; }

    for (int c = 0; c < G1_NC; c++) {
        int b = c % G1_STG;
        uint32_t ph = (c / G1_STG) & 1;
        mbar_wait(sb + 8 * b, ph);
        uint32_t Ab = sb + 1024 + b * G1_STAGE_B;
        uint32_t Bgb = Ab + 16384, Bub = Ab + 32768;
        #pragma unroll
        for (int kk = 0; kk < 64; kk += 16) {
            uint32_t a[4][4];
            #pragma unroll
            for (int mt = 0; mt < 4; mt++) {
                int m = wm * 64 + mt * 16 + (lane & 15);
                int colk = kk + (lane >> 4) * 8;
                ldm_x4(a[mt], Ab + m * 128 + ((colk * 2) ^ ((m & 7) << 4)));
            }
            uint32_t bG[2][4], bU[2][4];
            #pragma unroll
            for (int p = 0; p < 2; p++) {
                int krow = kk + (lane & 15);
                int coln = wn * 32 + p * 16 + (lane >> 4) * 8;
                uint32_t off = krow * 256 + ((coln * 2) ^ ((krow & 7) << 4));
                ldm_x4_t(bG[p], Bgb + off);
                ldm_x4_t(bU[p], Bub + off);
            }
            #pragma unroll
            for (int mt = 0; mt < 4; mt++)
                #pragma unroll
                for (int nt = 0; nt < 4; nt++) {
                    mma16816(accG[mt][nt], a[mt], &bG[nt >> 1][(nt & 1) * 2]);
                    mma16816(accU[mt][nt], a[mt], &bU[nt >> 1][(nt & 1) * 2]);
                }
        }
        __syncwarp();
        if (lane == 0) mbar_arrive(sb + 64 + 8 * b);   // this warp done with buffer b
        int cn = c + G1_STG;
        if (cn < G1_NC && w == (c & (G1_WARPS - 1)) && lane == 0) {
            mbar_wait(sb + 64 + 8 * b, ph);            // all warps done -> buffer free
            issue(cn);
        }
    }

    // epilogue: h = silu(g+bg)*(u+bu) -> fp16 H in A-block layout
    const float* bgp = bg + e * MDIM + n0 + wn * 32;
    const float* bup = bu + e * MDIM + n0 + wn * 32;
    #pragma unroll
    for (int nt = 0; nt < 4; nt++) {
        int colb = nt * 8 + (lane & 3) * 2;
        float b_g0 = bgp[colb], b_g1 = bgp[colb + 1];
        float b_u0 = bup[colb], b_u1 = bup[colb + 1];
        int col = n0 + wn * 32 + colb;          // global H column
        int kt = col >> 6, k2 = (col & 63) * 2;
        size_t blk = (size_t)(rt * 32 + kt) * 16384;
        #pragma unroll
        for (int mt = 0; mt < 4; mt++) {
            int m = wm * 64 + mt * 16 + (lane >> 2);
            float g0 = accG[mt][nt][0] + b_g0, g1 = accG[mt][nt][1] + b_g1;
            float u0 = accU[mt][nt][0] + b_u0, u1 = accU[mt][nt][1] + b_u1;
            float h0 = g0 / (1.f + __expf(-g0)) * u0;
            float h1 = g1 / (1.f + __expf(-g1)) * u1;
            *reinterpret_cast<__half2*>((char*)g_H + blk + m * 128 + (k2 ^ ((m & 7) << 4))) =
                __floats2half2_rn(h0, h1);
            int m2 = m + 8;
            float g2 = accG[mt][nt][2] + b_g0, g3 = accG[mt][nt][3] + b_g1;
            float u2 = accU[mt][nt][2] + b_u0, u3 = accU[mt][nt][3] + b_u1;
            float h2 = g2 / (1.f + __expf(-g2)) * u2;
            float h3 = g3 / (1.f + __expf(-g3)) * u3;
            *reinterpret_cast<__half2*>((char*)g_H + blk + m2 * 128 + (k2 ^ ((m2 & 7) << 4))) =
                __floats2half2_rn(h2, h3);
        }
    }
}

// ================= launch 5: GEMM2, 256 threads, 2 CTAs/SM, 3-stage, rotated issuer =================
#define G2_STG 3
#define G2_NC 32
#define G2_STAGE_B 32768
#define G2_SMEM (1024 + G2_STG * G2_STAGE_B)
#define G2_WARPS 8

__global__ void __launch_bounds__(256, 2) gemm2_kernel() {
    int e = g_tile_expert[blockIdx.y];
    if (e < 0) return;
    int rt = blockIdx.y, nt_ = blockIdx.x;
    int row0 = rt * 128, n0 = nt_ * 128;
    extern __shared__ char smc[];
    uint32_t sb = smem_u32(smc);
    int tid = threadIdx.x, lane = tid & 31, w = tid >> 5;
    int wm = w >> 2, wn = w & 3;

    const char* Ablk = (const char*)g_H  + (size_t)(rt * 32) * 16384;
    const char* Bblk = (const char*)g_Wo + (size_t)((e * 8 + nt_) * 32) * 16384;

    if (tid == 0) {
        #pragma unroll
        for (int s = 0; s < G2_STG; s++) {
            mbar_init(sb + 8 * s, 1);
            mbar_init(sb + 64 + 8 * s, G2_WARPS);
        }
    }
    __syncthreads();
    FENCE_ASYNC();

    auto issue = [&](int c) {
        int b = c % G2_STG;
        uint32_t mb = sb + 8 * b;
        uint32_t dst = sb + 1024 + b * G2_STAGE_B;
        mbar_expect_tx(mb, G2_STAGE_B);
        bulk_g2s(dst,         Ablk + (size_t)c * 16384, 16384, mb);
        bulk_g2s(dst + 16384, Bblk + (size_t)c * 16384, 16384, mb);
    };
    if (tid == 0) { issue(0); issue(1); issue(2); }

    float acc[4][4][4];
    #pragma unroll
    for (int mt = 0; mt < 4; mt++)
        #pragma unroll
        for (int nt = 0; nt < 4; nt++)
            #pragma unroll
            for (int q = 0; q < 4; q++) acc[mt][nt][q] = 0.f;

    for (int c = 0; c < G2_NC; c++) {
        int b = c % G2_STG;
        uint32_t ph = (c / G2_STG) & 1;
        mbar_wait(sb + 8 * b, ph);
        uint32_t Ab = sb + 1024 + b * G2_STAGE_B;
        uint32_t Bb = Ab + 16384;
        #pragma unroll
        for (int kk = 0; kk < 64; kk += 16) {
            uint32_t a[4][4];
            #pragma unroll
            for (int mt = 0; mt < 4; mt++) {
                int m = wm * 64 + mt * 16 + (lane & 15);
                int colk = kk + (lane >> 4) * 8;
                ldm_x4(a[mt], Ab + m * 128 + ((colk * 2) ^ ((m & 7) << 4)));
            }
            uint32_t bB[2][4];
            #pragma unroll
            for (int p = 0; p < 2; p++) {
                int krow = kk + (lane & 15);
                int coln = wn * 32 + p * 16 + (lane >> 4) * 8;
                ldm_x4_t(bB[p], Bb + krow * 256 + ((coln * 2) ^ ((krow & 7) << 4)));
            }
            #pragma unroll
            for (int mt = 0; mt < 4; mt++)
                #pragma unroll
                for (int nt = 0; nt < 4; nt++)
                    mma16816(acc[mt][nt], a[mt], &bB[nt >> 1][(nt & 1) * 2]);
        }
        __syncwarp();
        if (lane == 0) mbar_arrive(sb + 64 + 8 * b);
        int cn = c + G2_STG;
        if (cn < G2_NC && w == (c & (G2_WARPS - 1)) && lane == 0) {
            mbar_wait(sb + 64 + 8 * b, ph);
            issue(cn);
        }
    }

    #pragma unroll
    for (int nt = 0; nt < 4; nt++) {
        int colb = nt * 8 + (lane & 3) * 2;
        int col = n0 + wn * 32 + colb;
        #pragma unroll
        for (int mt = 0; mt < 4; mt++) {
            int row = row0 + wm * 64 + mt * 16 + (lane >> 2);
            float2 v0 = make_float2(acc[mt][nt][0], acc[mt][nt][1]);
            float2 v1 = make_float2(acc[mt][nt][2], acc[mt][nt][3]);
            *reinterpret_cast<float2*>(g_Y + (size_t)row * DDIM + col) = v0;
            *reinterpret_cast<float2*>(g_Y + (size_t)(row + 8) * DDIM + col) = v1;
        }
    }
}

// ---------------- launch 6: combine ----------------
__global__ void combine_kernel(float* __restrict__ out, const float* __restrict__ bo) {
    int t = blockIdx.x;
    int c = threadIdx.x * 4;
    int e1 = g_tok_e[2 * t], e2 = g_tok_e[2 * t + 1];
    int r1 = g_offsets[e1] + g_tok_slot[2 * t];
    int r2 = g_offsets[e2] + g_tok_slot[2 * t + 1];
    float w1 = g_tok_w[2 * t], w2 = g_tok_w[2 * t + 1];
    float4 y1 = *reinterpret_cast<const float4*>(&g_Y[(size_t)r1 * DDIM + c]);
    float4 y2 = *reinterpret_cast<const float4*>(&g_Y[(size_t)r2 * DDIM + c]);
    float4 b1 = *reinterpret_cast<const float4*>(&bo[e1 * DDIM + c]);
    float4 b2 = *reinterpret_cast<const float4*>(&bo[e2 * DDIM + c]);
    float4 o;
    o.x = w1 * (y1.x + b1.x) + w2 * (y2.x + b2.x);
    o.y = w1 * (y1.y + b1.y) + w2 * (y2.y + b2.y);
    o.z = w1 * (y1.z + b1.z) + w2 * (y2.z + b2.z);
    o.w = w1 * (y1.w + b1.w) + w2 * (y2.w + b2.w);
    *reinterpret_cast<float4*>(&out[(size_t)t * DDIM + c]) = o;
}

// ---------------- launch: single stream, 6 launches (gemm1 = #4, profiled) ----------------
extern "C" void kernel_launch(void* const* d_in, const int* in_sizes, int n_in,
                              void* d_out, int out_size) {
    const float* residual = (const float*)d_in[0];
    const float* Wr = (const float*)d_in[1];
    const float* Wg = (const float*)d_in[2];
    const float* bg = (const float*)d_in[3];
    const float* Wu = (const float*)d_in[4];
    const float* bu = (const float*)d_in[5];
    const float* Wo = (const float*)d_in[6];
    const float* bo = (const float*)d_in[7];
    float* out = (float*)d_out;

    static bool attr_set = false;
    if (!attr_set) {
        cudaFuncSetAttribute(gemm1_kernel, cudaFuncAttributeMaxDynamicSharedMemorySize, G1_SMEM);
        cudaFuncSetAttribute(gemm2_kernel, cudaFuncAttributeMaxDynamicSharedMemorySize, G2_SMEM);
        attr_set = true;
    }

    dim3 cg(2048, 3);
    convert_kernel<<<cg, 256>>>(Wg, Wu, Wo);                 // 1
    router_kernel<<<T_TOKENS / RT_TPB, 256>>>(residual, Wr); // 2
    sg_kernel<<<T_TOKENS * 2, 128>>>(residual);              // 3
    dim3 g1(MDIM / 128, MAX_TILES);
    gemm1_kernel<<<g1, 256, G1_SMEM>>>(bg, bu);              // 4  <-- profiled, 256 thr / 64x32 warps
    dim3 g2(DDIM / 128, MAX_TILES);
    gemm2_kernel<<<g2, 256, G2_SMEM>>>();                    // 5
    combine_kernel<<<T_TOKENS, 256>>>(out, bo);              // 6
}

// round 16
// speedup vs baseline: 1.0441x; 1.0441x over previous
#include <cuda_runtime.h>
#include <cuda_fp16.h>
#include <cstdint>

#define T_TOKENS 4096
#define DDIM 1024
#define MDIM 2048
#define NEXP 8
#define ROWS_PAD 9216      // 72 tiles * 128 rows
#define MAX_TILES 72

// Block layout: all GEMM operands stored as 16KB blocks of (64 k) x (128 n/m),
// A blocks: 128 m x 64 k, element (m,k) at byte m*128 + ((k*2) ^ ((m&7)<<4))
// B blocks: 64 k x 128 n, element (k,n) at byte k*256 + ((n*2) ^ ((k&7)<<4))
__device__ __half g_Wg[NEXP * DDIM * MDIM];
__device__ __half g_Wu[NEXP * DDIM * MDIM];
__device__ __half g_Wo[NEXP * MDIM * DDIM];
__device__ __half g_X[ROWS_PAD * DDIM];
__device__ __half g_H[ROWS_PAD * MDIM];
__device__ int    g_counts[NEXP];
__device__ int    g_row_tok[ROWS_PAD];
__device__ float  g_row_w[ROWS_PAD];
__device__ int    g_tile_expert[MAX_TILES];
__device__ int    g_tok_e[T_TOKENS * 2];
__device__ int    g_tok_slot[T_TOKENS * 2];
__device__ float  g_tok_w[T_TOKENS * 2];

// ---------------- helpers ----------------
__device__ __forceinline__ uint32_t smem_u32(const void* p) {
    uint32_t a;
    asm("{ .reg .u64 t; cvta.to.shared.u64 t, %1; cvt.u32.u64 %0, t; }" : "=r"(a) : "l"(p));
    return a;
}
__device__ __forceinline__ void mbar_init(uint32_t a, uint32_t cnt) {
    asm volatile("mbarrier.init.shared.b64 [%0], %1;" :: "r"(a), "r"(cnt) : "memory");
}
__device__ __forceinline__ void mbar_arrive(uint32_t a) {
    asm volatile("mbarrier.arrive.shared.b64 _, [%0];" :: "r"(a) : "memory");
}
__device__ __forceinline__ void mbar_expect_tx(uint32_t a, uint32_t bytes) {
    asm volatile("mbarrier.arrive.expect_tx.shared.b64 _, [%0], %1;" :: "r"(a), "r"(bytes) : "memory");
}
__device__ __forceinline__ void bulk_g2s(uint32_t dst, const void* src, uint32_t bytes, uint32_t mbar) {
    asm volatile("cp.async.bulk.shared::cta.global.mbarrier::complete_tx::bytes [%0], [%1], %2, [%3];"
                 :: "r"(dst), "l"(src), "r"(bytes), "r"(mbar) : "memory");
}
__device__ __forceinline__ void mbar_wait(uint32_t a, uint32_t parity) {
    asm volatile(
        "{\n\t.reg .pred P1;\n\t"
        "W%=:\n\t"
        "mbarrier.try_wait.parity.acquire.cta.shared::cta.b64 P1, [%0], %1, 0x989680;\n\t"
        "@P1 bra.uni D%=;\n\t"
        "bra.uni W%=;\n\t"
        "D%=:\n\t}"
        :: "r"(a), "r"(parity) : "memory");
}
#define FENCE_ASYNC() asm volatile("fence.proxy.async.shared::cta;" ::: "memory")
__device__ __forceinline__ void ldm_x4(uint32_t* r, uint32_t addr) {
    asm volatile("ldmatrix.sync.aligned.m8n8.x4.shared.b16 {%0,%1,%2,%3}, [%4];"
                 : "=r"(r[0]), "=r"(r[1]), "=r"(r[2]), "=r"(r[3]) : "r"(addr));
}
__device__ __forceinline__ void ldm_x4_t(uint32_t* r, uint32_t addr) {
    asm volatile("ldmatrix.sync.aligned.m8n8.x4.trans.shared.b16 {%0,%1,%2,%3}, [%4];"
                 : "=r"(r[0]), "=r"(r[1]), "=r"(r[2]), "=r"(r[3]) : "r"(addr));
}
__device__ __forceinline__ void mma16816(float* c, const uint32_t* a, const uint32_t* b) {
    asm volatile(
        "mma.sync.aligned.m16n8k16.row.col.f32.f16.f16.f32 "
        "{%0,%1,%2,%3}, {%4,%5,%6,%7}, {%8,%9}, {%0,%1,%2,%3};"
        : "+f"(c[0]), "+f"(c[1]), "+f"(c[2]), "+f"(c[3])
        : "r"(a[0]), "r"(a[1]), "r"(a[2]), "r"(a[3]), "r"(b[0]), "r"(b[1]));
}

// ---------------- launch 1: convert all weights + zero counts + zero X + init row_tok ----------------
__device__ __forceinline__ void convert_body(const float* __restrict__ src,
                                             __half* __restrict__ dst,
                                             int KD, int ND, int x) {
    __shared__ float tile[64][128];
    int NT = ND / 128, KT = KD / 64;
    int e = x / (NT * KT);
    int nt = (x / KT) % NT;
    int kt = x % KT;
    int k0 = kt * 64, n0 = nt * 128;
    int tid = threadIdx.x;              // 256
    const float* s = src + (size_t)e * KD * ND;
    #pragma unroll
    for (int i = 0; i < 8; i++) {
        int idx = tid + i * 256;        // 2048 float4
        int k = idx >> 5, nq = (idx & 31) * 4;
        float4 v = *reinterpret_cast<const float4*>(s + (size_t)(k0 + k) * ND + n0 + nq);
        *reinterpret_cast<float4*>(&tile[k][nq]) = v;
    }
    __syncthreads();
    uint4* out = reinterpret_cast<uint4*>(dst + (size_t)x * 8192);
    #pragma unroll
    for (int i = 0; i < 4; i++) {
        int idx = tid + i * 256;        // 1024 uint4
        int k = idx >> 4;
        int wb = (idx & 15) * 16;
        int n = (wb ^ ((k & 7) << 4)) >> 1;
        float4 v0 = *reinterpret_cast<const float4*>(&tile[k][n]);
        float4 v1 = *reinterpret_cast<const float4*>(&tile[k][n + 4]);
        __half2 h[4];
        h[0] = __floats2half2_rn(v0.x, v0.y);
        h[1] = __floats2half2_rn(v0.z, v0.w);
        h[2] = __floats2half2_rn(v1.x, v1.y);
        h[3] = __floats2half2_rn(v1.z, v1.w);
        out[idx] = *reinterpret_cast<uint4*>(h);
    }
}

__global__ void convert_kernel(const float* __restrict__ wg,
                               const float* __restrict__ wu,
                               const float* __restrict__ wo) {
    int flat = (blockIdx.y * gridDim.x + blockIdx.x) * blockDim.x + threadIdx.x;
    if (flat < NEXP) g_counts[flat] = 0;
    if (flat < ROWS_PAD) g_row_tok[flat] = -1;
    const int nx = ROWS_PAD * DDIM / 8;
    if (flat < nx) reinterpret_cast<uint4*>(g_X)[flat] = make_uint4(0, 0, 0, 0);

    if (blockIdx.y == 0)      convert_body(wg, g_Wg, DDIM, MDIM, blockIdx.x);
    else if (blockIdx.y == 1) convert_body(wu, g_Wu, DDIM, MDIM, blockIdx.x);
    else                      convert_body(wo, g_Wo, MDIM, DDIM, blockIdx.x);
}

// ---------------- launch 2: router ----------------
#define RT_TPB 16
__global__ void __launch_bounds__(256) router_kernel(const float* __restrict__ residual,
                                                     const float* __restrict__ Wr) {
    __shared__ float wrT[NEXP][DDIM];
    __shared__ float xs[DDIM];
    __shared__ float logits[NEXP];
    int tid = threadIdx.x, w = tid >> 5, lane = tid & 31;
    #pragma unroll
    for (int i = 0; i < 32; i++) {
        int idx = tid + i * 256;
        wrT[idx & 7][idx >> 3] = Wr[idx];
    }
    __syncthreads();
    const float4* wr4 = reinterpret_cast<const float4*>(&wrT[w][0]);
    for (int tt = 0; tt < RT_TPB; tt++) {
        int t = blockIdx.x * RT_TPB + tt;
        reinterpret_cast<float4*>(xs)[tid] =
            reinterpret_cast<const float4*>(residual + (size_t)t * DDIM)[tid];
        __syncthreads();
        const float4* xs4 = reinterpret_cast<const float4*>(xs);
        float s = 0.f;
        #pragma unroll
        for (int j = 0; j < 8; j++) {
            float4 xv = xs4[j * 32 + lane];
            float4 wv = wr4[j * 32 + lane];
            s += xv.x * wv.x + xv.y * wv.y + xv.z * wv.z + xv.w * wv.w;
        }
        #pragma unroll
        for (int o = 16; o > 0; o >>= 1) s += __shfl_xor_sync(0xffffffff, s, o);
        if (lane == 0) logits[w] = s;
        __syncthreads();
        if (tid == 0) {
            float mx = logits[0];
            #pragma unroll
            for (int e = 1; e < NEXP; e++) mx = fmaxf(mx, logits[e]);
            float p[NEXP]; float sum = 0.f;
            #pragma unroll
            for (int e = 0; e < NEXP; e++) { p[e] = expf(logits[e] - mx); sum += p[e]; }
            #pragma unroll
            for (int e = 0; e < NEXP; e++) p[e] /= sum;
            int i1 = 0;
            #pragma unroll
            for (int e = 1; e < NEXP; e++) if (p[e] > p[i1]) i1 = e;
            int i2 = -1;
            #pragma unroll
            for (int e = 0; e < NEXP; e++) {
                if (e == i1) continue;
                if (i2 < 0 || p[e] > p[i2]) i2 = e;
            }
            float w1 = p[i1], w2 = p[i2];
            float inv = 1.f / (w1 + w2 + 1e-8f);
            w1 *= inv; w2 *= inv;
            int s1 = atomicAdd(&g_counts[i1], 1);
            int s2 = atomicAdd(&g_counts[i2], 1);
            g_tok_e[2 * t] = i1;     g_tok_e[2 * t + 1] = i2;
            g_tok_slot[2 * t] = s1;  g_tok_slot[2 * t + 1] = s2;
            g_tok_w[2 * t] = w1;     g_tok_w[2 * t + 1] = w2;
        }
        __syncthreads();
    }
}

// ---------------- launch 3: fused scatter+gather + zero out ----------------
__global__ void sg_kernel(const float* __restrict__ residual, float* __restrict__ out) {
    int i = blockIdx.x;                 // 8192 blocks
    int tid = threadIdx.x;              // 128
    if (i == 0 && tid == 0) {
        int tile = 0;
        #pragma unroll
        for (int e = 0; e < NEXP; e++) {
            int nt = (g_counts[e] + 127) >> 7;
            for (int k = 0; k < nt; k++) g_tile_expert[tile++] = e;
        }
        for (; tile < MAX_TILES; tile++) g_tile_expert[tile] = -1;
    }
    // zero out: 8192 blocks x 128 threads = 1,048,576 uint4 = 16 MB = full out
    reinterpret_cast<uint4*>(out)[(size_t)i * 128 + tid] = make_uint4(0, 0, 0, 0);

    int e = g_tok_e[i];
    int off = 0;
    #pragma unroll
    for (int q = 0; q < NEXP; q++)
        if (q < e) off += ((g_counts[q] + 127) >> 7) << 7;
    int row = off + g_tok_slot[i];
    int tok = i >> 1;
    if (tid == 0) {
        g_row_tok[row] = tok;
        g_row_w[row] = g_tok_w[i];
    }
    int c = tid * 8;
    const float4* src = reinterpret_cast<const float4*>(residual + (size_t)tok * DDIM + c);
    float4 a = src[0], b = src[1];
    __half2 h[4];
    h[0] = __floats2half2_rn(a.x, a.y); h[1] = __floats2half2_rn(a.z, a.w);
    h[2] = __floats2half2_rn(b.x, b.y); h[3] = __floats2half2_rn(b.z, b.w);
    int rt = row >> 7, m = row & 127;
    int kt = c >> 6, k = c & 63;
    reinterpret_cast<uint4*>(g_X)[(size_t)(rt * 16 + kt) * 1024 + m * 8 + ((k >> 3) ^ (m & 7))] =
        *reinterpret_cast<uint4*>(h);
}

// ================= launch 4 (PROFILED): GEMM1, R14 config: 512 thr, 4x4 warps 32x32, 4-stage =================
#define G1_STG 4
#define G1_NC 16
#define G1_STAGE_B 49152
#define G1_SMEM (1024 + G1_STG * G1_STAGE_B)
#define G1_WARPS 16

__global__ void __launch_bounds__(512, 1) gemm1_kernel(const float* __restrict__ bg,
                                                       const float* __restrict__ bu) {
    int e = g_tile_expert[blockIdx.y];
    if (e < 0) return;
    int rt = blockIdx.y, nt_ = blockIdx.x;
    int n0 = nt_ * 128;
    extern __shared__ char smc[];
    uint32_t sb = smem_u32(smc);
    int tid = threadIdx.x, lane = tid & 31, w = tid >> 5;
    int wm = w >> 2, wn = w & 3;        // 4x4 warps, 32x32 each

    const char* Ablk  = (const char*)g_X  + (size_t)(rt * 16) * 16384;
    const char* Bgblk = (const char*)g_Wg + (size_t)((e * 16 + nt_) * 16) * 16384;
    const char* Bublk = (const char*)g_Wu + (size_t)((e * 16 + nt_) * 16) * 16384;

    if (tid == 0) {
        #pragma unroll
        for (int s = 0; s < G1_STG; s++) {
            mbar_init(sb + 8 * s, 1);                 // full
            mbar_init(sb + 64 + 8 * s, G1_WARPS);     // empty (one arrive per warp)
        }
    }
    __syncthreads();
    FENCE_ASYNC();

    auto issue = [&](int c) {
        int b = c % G1_STG;
        uint32_t mb = sb + 8 * b;
        uint32_t dst = sb + 1024 + b * G1_STAGE_B;
        mbar_expect_tx(mb, G1_STAGE_B);
        bulk_g2s(dst,          Ablk  + (size_t)c * 16384, 16384, mb);
        bulk_g2s(dst + 16384,  Bgblk + (size_t)c * 16384, 16384, mb);
        bulk_g2s(dst + 32768,  Bublk + (size_t)c * 16384, 16384, mb);
    };
    if (tid == 0) { issue(0); issue(1); issue(2); issue(3); }

    float accG[2][4][4], accU[2][4][4];
    #pragma unroll
    for (int mt = 0; mt < 2; mt++)
        #pragma unroll
        for (int nt = 0; nt < 4; nt++)
            #pragma unroll
            for (int q = 0; q < 4; q++) { accG[mt][nt][q] = 0.f; accU[mt][nt][q] = 0.f; }

    for (int c = 0; c < G1_NC; c++) {
        int b = c % G1_STG;
        uint32_t ph = (c / G1_STG) & 1;
        mbar_wait(sb + 8 * b, ph);
        uint32_t Ab = sb + 1024 + b * G1_STAGE_B;
        uint32_t Bgb = Ab + 16384, Bub = Ab + 32768;
        #pragma unroll
        for (int kk = 0; kk < 64; kk += 16) {
            uint32_t a[2][4];
            #pragma unroll
            for (int mt = 0; mt < 2; mt++) {
                int m = wm * 32 + mt * 16 + (lane & 15);
                int colk = kk + (lane >> 4) * 8;
                ldm_x4(a[mt], Ab + m * 128 + ((colk * 2) ^ ((m & 7) << 4)));
            }
            uint32_t bG[2][4], bU[2][4];
            #pragma unroll
            for (int p = 0; p < 2; p++) {
                int krow = kk + (lane & 15);
                int coln = wn * 32 + p * 16 + (lane >> 4) * 8;
                uint32_t off = krow * 256 + ((coln * 2) ^ ((krow & 7) << 4));
                ldm_x4_t(bG[p], Bgb + off);
                ldm_x4_t(bU[p], Bub + off);
            }
            #pragma unroll
            for (int mt = 0; mt < 2; mt++)
                #pragma unroll
                for (int nt = 0; nt < 4; nt++) {
                    mma16816(accG[mt][nt], a[mt], &bG[nt >> 1][(nt & 1) * 2]);
                    mma16816(accU[mt][nt], a[mt], &bU[nt >> 1][(nt & 1) * 2]);
                }
        }
        __syncwarp();
        if (lane == 0) mbar_arrive(sb + 64 + 8 * b);
        int cn = c + G1_STG;
        if (cn < G1_NC && w == (c & (G1_WARPS - 1)) && lane == 0) {
            mbar_wait(sb + 64 + 8 * b, ph);
            issue(cn);
        }
    }

    // epilogue: h = silu(g+bg)*(u+bu) -> fp16 H in A-block layout
    const float* bgp = bg + e * MDIM + n0 + wn * 32;
    const float* bup = bu + e * MDIM + n0 + wn * 32;
    #pragma unroll
    for (int nt = 0; nt < 4; nt++) {
        int colb = nt * 8 + (lane & 3) * 2;
        float b_g0 = bgp[colb], b_g1 = bgp[colb + 1];
        float b_u0 = bup[colb], b_u1 = bup[colb + 1];
        int col = n0 + wn * 32 + colb;
        int kt = col >> 6, k2 = (col & 63) * 2;
        size_t blk = (size_t)(rt * 32 + kt) * 16384;
        #pragma unroll
        for (int mt = 0; mt < 2; mt++) {
            int m = wm * 32 + mt * 16 + (lane >> 2);
            float g0 = accG[mt][nt][0] + b_g0, g1 = accG[mt][nt][1] + b_g1;
            float u0 = accU[mt][nt][0] + b_u0, u1 = accU[mt][nt][1] + b_u1;
            float h0 = g0 / (1.f + __expf(-g0)) * u0;
            float h1 = g1 / (1.f + __expf(-g1)) * u1;
            *reinterpret_cast<__half2*>((char*)g_H + blk + m * 128 + (k2 ^ ((m & 7) << 4))) =
                __floats2half2_rn(h0, h1);
            int m2 = m + 8;
            float g2 = accG[mt][nt][2] + b_g0, g3 = accG[mt][nt][3] + b_g1;
            float u2 = accU[mt][nt][2] + b_u0, u3 = accU[mt][nt][3] + b_u1;
            float h2 = g2 / (1.f + __expf(-g2)) * u2;
            float h3 = g3 / (1.f + __expf(-g3)) * u3;
            *reinterpret_cast<__half2*>((char*)g_H + blk + m2 * 128 + (k2 ^ ((m2 & 7) << 4))) =
                __floats2half2_rn(h2, h3);
        }
    }
}

// ================= launch 5: GEMM2 + fused combine (atomic 2-term add), 2 CTAs/SM =================
#define G2_STG 3
#define G2_NC 32
#define G2_STAGE_B 32768
#define G2_SMEM (1024 + G2_STG * G2_STAGE_B)
#define G2_WARPS 8

__global__ void __launch_bounds__(256, 2) gemm2_kernel(float* __restrict__ out,
                                                       const float* __restrict__ bo) {
    int e = g_tile_expert[blockIdx.y];
    if (e < 0) return;
    int rt = blockIdx.y, nt_ = blockIdx.x;
    int row0 = rt * 128, n0 = nt_ * 128;
    extern __shared__ char smc[];
    uint32_t sb = smem_u32(smc);
    int tid = threadIdx.x, lane = tid & 31, w = tid >> 5;
    int wm = w >> 2, wn = w & 3;

    const char* Ablk = (const char*)g_H  + (size_t)(rt * 32) * 16384;
    const char* Bblk = (const char*)g_Wo + (size_t)((e * 8 + nt_) * 32) * 16384;

    if (tid == 0) {
        #pragma unroll
        for (int s = 0; s < G2_STG; s++) {
            mbar_init(sb + 8 * s, 1);
            mbar_init(sb + 64 + 8 * s, G2_WARPS);
        }
    }
    __syncthreads();
    FENCE_ASYNC();

    auto issue = [&](int c) {
        int b = c % G2_STG;
        uint32_t mb = sb + 8 * b;
        uint32_t dst = sb + 1024 + b * G2_STAGE_B;
        mbar_expect_tx(mb, G2_STAGE_B);
        bulk_g2s(dst,         Ablk + (size_t)c * 16384, 16384, mb);
        bulk_g2s(dst + 16384, Bblk + (size_t)c * 16384, 16384, mb);
    };
    if (tid == 0) { issue(0); issue(1); issue(2); }

    float acc[4][4][4];
    #pragma unroll
    for (int mt = 0; mt < 4; mt++)
        #pragma unroll
        for (int nt = 0; nt < 4; nt++)
            #pragma unroll
            for (int q = 0; q < 4; q++) acc[mt][nt][q] = 0.f;

    for (int c = 0; c < G2_NC; c++) {
        int b = c % G2_STG;
        uint32_t ph = (c / G2_STG) & 1;
        mbar_wait(sb + 8 * b, ph);
        uint32_t Ab = sb + 1024 + b * G2_STAGE_B;
        uint32_t Bb = Ab + 16384;
        #pragma unroll
        for (int kk = 0; kk < 64; kk += 16) {
            uint32_t a[4][4];
            #pragma unroll
            for (int mt = 0; mt < 4; mt++) {
                int m = wm * 64 + mt * 16 + (lane & 15);
                int colk = kk + (lane >> 4) * 8;
                ldm_x4(a[mt], Ab + m * 128 + ((colk * 2) ^ ((m & 7) << 4)));
            }
            uint32_t bB[2][4];
            #pragma unroll
            for (int p = 0; p < 2; p++) {
                int krow = kk + (lane & 15);
                int coln = wn * 32 + p * 16 + (lane >> 4) * 8;
                ldm_x4_t(bB[p], Bb + krow * 256 + ((coln * 2) ^ ((krow & 7) << 4)));
            }
            #pragma unroll
            for (int mt = 0; mt < 4; mt++)
                #pragma unroll
                for (int nt = 0; nt < 4; nt++)
                    mma16816(acc[mt][nt], a[mt], &bB[nt >> 1][(nt & 1) * 2]);
        }
        __syncwarp();
        if (lane == 0) mbar_arrive(sb + 64 + 8 * b);
        int cn = c + G2_STG;
        if (cn < G2_NC && w == (c & (G2_WARPS - 1)) && lane == 0) {
            mbar_wait(sb + 64 + 8 * b, ph);
            issue(cn);
        }
    }

    // epilogue: fused combine -- out[tok] += w * (acc + bo[e])   (2 contributions per token,
    // IEEE-add of two terms is order-invariant => deterministic)
    const float* bop = bo + e * DDIM;
    #pragma unroll
    for (int mt = 0; mt < 4; mt++) {
        int row = row0 + wm * 64 + mt * 16 + (lane >> 2);
        int tok0 = g_row_tok[row];
        float w0 = g_row_w[row];
        int tok1 = g_row_tok[row + 8];
        float w1 = g_row_w[row + 8];
        #pragma unroll
        for (int nt = 0; nt < 4; nt++) {
            int col = n0 + wn * 32 + nt * 8 + (lane & 3) * 2;
            float b0 = bop[col], b1 = bop[col + 1];
            if (tok0 >= 0) {
                float* dst = out + (size_t)tok0 * DDIM + col;
                atomicAdd(dst,     w0 * (acc[mt][nt][0] + b0));
                atomicAdd(dst + 1, w0 * (acc[mt][nt][1] + b1));
            }
            if (tok1 >= 0) {
                float* dst = out + (size_t)tok1 * DDIM + col;
                atomicAdd(dst,     w1 * (acc[mt][nt][2] + b0));
                atomicAdd(dst + 1, w1 * (acc[mt][nt][3] + b1));
            }
        }
    }
}

// ---------------- launch: single stream, 5 launches (gemm1 = #4, profiled) ----------------
extern "C" void kernel_launch(void* const* d_in, const int* in_sizes, int n_in,
                              void* d_out, int out_size) {
    const float* residual = (const float*)d_in[0];
    const float* Wr = (const float*)d_in[1];
    const float* Wg = (const float*)d_in[2];
    const float* bg = (const float*)d_in[3];
    const float* Wu = (const float*)d_in[4];
    const float* bu = (const float*)d_in[5];
    const float* Wo = (const float*)d_in[6];
    const float* bo = (const float*)d_in[7];
    float* out = (float*)d_out;

    static bool attr_set = false;
    if (!attr_set) {
        cudaFuncSetAttribute(gemm1_kernel, cudaFuncAttributeMaxDynamicSharedMemorySize, G1_SMEM);
        cudaFuncSetAttribute(gemm2_kernel, cudaFuncAttributeMaxDynamicSharedMemorySize, G2_SMEM);
        attr_set = true;
    }

    dim3 cg(2048, 3);
    convert_kernel<<<cg, 256>>>(Wg, Wu, Wo);                 // 1
    router_kernel<<<T_TOKENS / RT_TPB, 256>>>(residual, Wr); // 2
    sg_kernel<<<T_TOKENS * 2, 128>>>(residual, out);         // 3 (also zeroes out)
    dim3 g1(MDIM / 128, MAX_TILES);
    gemm1_kernel<<<g1, 512, G1_SMEM>>>(bg, bu);              // 4  <-- profiled (R14 config)
    dim3 g2(DDIM / 128, MAX_TILES);
    gemm2_kernel<<<g2, 256, G2_SMEM>>>(out, bo);             // 5 (fused combine)
}

// round 17
// speedup vs baseline: 1.1178x; 1.0706x over previous
#include <cuda_runtime.h>
#include <cuda_fp16.h>
#include <cstdint>

#define T_TOKENS 4096
#define DDIM 1024
#define MDIM 2048
#define NEXP 8
#define ROWS_PAD 9216      // 72 tiles * 128 rows
#define MAX_TILES 72

// Block layout: all GEMM operands stored as 16KB blocks of (64 k) x (128 n/m),
// A blocks: 128 m x 64 k, element (m,k) at byte m*128 + ((k*2) ^ ((m&7)<<4))
// B blocks: 64 k x 128 n, element (k,n) at byte k*256 + ((n*2) ^ ((k&7)<<4))
__device__ __half g_Wg[NEXP * DDIM * MDIM];
__device__ __half g_Wu[NEXP * DDIM * MDIM];
__device__ __half g_Wo[NEXP * MDIM * DDIM];
__device__ __half g_X[ROWS_PAD * DDIM];
__device__ __half g_H[ROWS_PAD * MDIM];
__device__ int    g_counts[NEXP];
__device__ int    g_row_tok[ROWS_PAD];
__device__ float  g_row_w[ROWS_PAD];
__device__ int    g_tile_expert[MAX_TILES];
__device__ int    g_tok_e[T_TOKENS * 2];
__device__ int    g_tok_slot[T_TOKENS * 2];
__device__ float  g_tok_w[T_TOKENS * 2];

// ---------------- helpers ----------------
__device__ __forceinline__ uint32_t smem_u32(const void* p) {
    uint32_t a;
    asm("{ .reg .u64 t; cvta.to.shared.u64 t, %1; cvt.u32.u64 %0, t; }" : "=r"(a) : "l"(p));
    return a;
}
__device__ __forceinline__ void mbar_init(uint32_t a, uint32_t cnt) {
    asm volatile("mbarrier.init.shared.b64 [%0], %1;" :: "r"(a), "r"(cnt) : "memory");
}
__device__ __forceinline__ void mbar_arrive(uint32_t a) {
    asm volatile("mbarrier.arrive.shared.b64 _, [%0];" :: "r"(a) : "memory");
}
__device__ __forceinline__ void mbar_expect_tx(uint32_t a, uint32_t bytes) {
    asm volatile("mbarrier.arrive.expect_tx.shared.b64 _, [%0], %1;" :: "r"(a), "r"(bytes) : "memory");
}
__device__ __forceinline__ void bulk_g2s(uint32_t dst, const void* src, uint32_t bytes, uint32_t mbar) {
    asm volatile("cp.async.bulk.shared::cta.global.mbarrier::complete_tx::bytes [%0], [%1], %2, [%3];"
                 :: "r"(dst), "l"(src), "r"(bytes), "r"(mbar) : "memory");
}
__device__ __forceinline__ void mbar_wait(uint32_t a, uint32_t parity) {
    asm volatile(
        "{\n\t.reg .pred P1;\n\t"
        "W%=:\n\t"
        "mbarrier.try_wait.parity.acquire.cta.shared::cta.b64 P1, [%0], %1, 0x989680;\n\t"
        "@P1 bra.uni D%=;\n\t"
        "bra.uni W%=;\n\t"
        "D%=:\n\t}"
        :: "r"(a), "r"(parity) : "memory");
}
#define FENCE_ASYNC() asm volatile("fence.proxy.async.shared::cta;" ::: "memory")
__device__ __forceinline__ void ldm_x4(uint32_t* r, uint32_t addr) {
    asm volatile("ldmatrix.sync.aligned.m8n8.x4.shared.b16 {%0,%1,%2,%3}, [%4];"
                 : "=r"(r[0]), "=r"(r[1]), "=r"(r[2]), "=r"(r[3]) : "r"(addr));
}
__device__ __forceinline__ void ldm_x4_t(uint32_t* r, uint32_t addr) {
    asm volatile("ldmatrix.sync.aligned.m8n8.x4.trans.shared.b16 {%0,%1,%2,%3}, [%4];"
                 : "=r"(r[0]), "=r"(r[1]), "=r"(r[2]), "=r"(r[3]) : "r"(addr));
}
__device__ __forceinline__ void mma16816(float* c, const uint32_t* a, const uint32_t* b) {
    asm volatile(
        "mma.sync.aligned.m16n8k16.row.col.f32.f16.f16.f32 "
        "{%0,%1,%2,%3}, {%4,%5,%6,%7}, {%8,%9}, {%0,%1,%2,%3};"
        : "+f"(c[0]), "+f"(c[1]), "+f"(c[2]), "+f"(c[3])
        : "r"(a[0]), "r"(a[1]), "r"(a[2]), "r"(a[3]), "r"(b[0]), "r"(b[1]));
}

// ---------------- convert body: fp32 [E][K][N] tile -> swizzled fp16 B-block ----------------
__device__ __forceinline__ void convert_body(const float* __restrict__ src,
                                             __half* __restrict__ dst,
                                             int KD, int ND, int x) {
    __shared__ float tile[64][128];
    int NT = ND / 128, KT = KD / 64;
    int e = x / (NT * KT);
    int nt = (x / KT) % NT;
    int kt = x % KT;
    int k0 = kt * 64, n0 = nt * 128;
    int tid = threadIdx.x;              // 256
    const float* s = src + (size_t)e * KD * ND;
    #pragma unroll
    for (int i = 0; i < 8; i++) {
        int idx = tid + i * 256;        // 2048 float4
        int k = idx >> 5, nq = (idx & 31) * 4;
        float4 v = *reinterpret_cast<const float4*>(s + (size_t)(k0 + k) * ND + n0 + nq);
        *reinterpret_cast<float4*>(&tile[k][nq]) = v;
    }
    __syncthreads();
    uint4* out = reinterpret_cast<uint4*>(dst + (size_t)x * 8192);
    #pragma unroll
    for (int i = 0; i < 4; i++) {
        int idx = tid + i * 256;        // 1024 uint4
        int k = idx >> 4;
        int wb = (idx & 15) * 16;
        int n = (wb ^ ((k & 7) << 4)) >> 1;
        float4 v0 = *reinterpret_cast<const float4*>(&tile[k][n]);
        float4 v1 = *reinterpret_cast<const float4*>(&tile[k][n + 4]);
        __half2 h[4];
        h[0] = __floats2half2_rn(v0.x, v0.y);
        h[1] = __floats2half2_rn(v0.z, v0.w);
        h[2] = __floats2half2_rn(v1.x, v1.y);
        h[3] = __floats2half2_rn(v1.z, v1.w);
        out[idx] = *reinterpret_cast<uint4*>(h);
    }
}

// ---------------- launch 1 (main): convert gate+up + zero counts/X/row_tok ----------------
__global__ void convert_gu_kernel(const float* __restrict__ wg,
                                  const float* __restrict__ wu) {
    int flat = (blockIdx.y * gridDim.x + blockIdx.x) * blockDim.x + threadIdx.x;
    const int total = 2048 * 2 * 256;   // 1,048,576
    if (flat < NEXP) g_counts[flat] = 0;
    if (flat < ROWS_PAD) g_row_tok[flat] = -1;
    const int nx = ROWS_PAD * DDIM / 8; // 1,179,648 uint4
    for (int idx = flat; idx < nx; idx += total)
        reinterpret_cast<uint4*>(g_X)[idx] = make_uint4(0, 0, 0, 0);

    if (blockIdx.y == 0) convert_body(wg, g_Wg, DDIM, MDIM, blockIdx.x);
    else                 convert_body(wu, g_Wu, DDIM, MDIM, blockIdx.x);
}

// ---------------- side stream: convert out-weights (runs under GEMM1) ----------------
__global__ void convert_o_kernel(const float* __restrict__ wo) {
    convert_body(wo, g_Wo, MDIM, DDIM, blockIdx.x);
}

// ---------------- launch 2: router (4 tokens/block -> 1024 blocks) ----------------
#define RT_TPB 4
__global__ void __launch_bounds__(256) router_kernel(const float* __restrict__ residual,
                                                     const float* __restrict__ Wr) {
    __shared__ float wrT[NEXP][DDIM];
    __shared__ float xs[DDIM];
    __shared__ float logits[NEXP];
    int tid = threadIdx.x, w = tid >> 5, lane = tid & 31;
    #pragma unroll
    for (int i = 0; i < 32; i++) {
        int idx = tid + i * 256;
        wrT[idx & 7][idx >> 3] = Wr[idx];
    }
    __syncthreads();
    const float4* wr4 = reinterpret_cast<const float4*>(&wrT[w][0]);
    for (int tt = 0; tt < RT_TPB; tt++) {
        int t = blockIdx.x * RT_TPB + tt;
        reinterpret_cast<float4*>(xs)[tid] =
            reinterpret_cast<const float4*>(residual + (size_t)t * DDIM)[tid];
        __syncthreads();
        const float4* xs4 = reinterpret_cast<const float4*>(xs);
        float s = 0.f;
        #pragma unroll
        for (int j = 0; j < 8; j++) {
            float4 xv = xs4[j * 32 + lane];
            float4 wv = wr4[j * 32 + lane];
            s += xv.x * wv.x + xv.y * wv.y + xv.z * wv.z + xv.w * wv.w;
        }
        #pragma unroll
        for (int o = 16; o > 0; o >>= 1) s += __shfl_xor_sync(0xffffffff, s, o);
        if (lane == 0) logits[w] = s;
        __syncthreads();
        if (tid == 0) {
            float mx = logits[0];
            #pragma unroll
            for (int e = 1; e < NEXP; e++) mx = fmaxf(mx, logits[e]);
            float p[NEXP]; float sum = 0.f;
            #pragma unroll
            for (int e = 0; e < NEXP; e++) { p[e] = expf(logits[e] - mx); sum += p[e]; }
            #pragma unroll
            for (int e = 0; e < NEXP; e++) p[e] /= sum;
            int i1 = 0;
            #pragma unroll
            for (int e = 1; e < NEXP; e++) if (p[e] > p[i1]) i1 = e;
            int i2 = -1;
            #pragma unroll
            for (int e = 0; e < NEXP; e++) {
                if (e == i1) continue;
                if (i2 < 0 || p[e] > p[i2]) i2 = e;
            }
            float w1 = p[i1], w2 = p[i2];
            float inv = 1.f / (w1 + w2 + 1e-8f);
            w1 *= inv; w2 *= inv;
            int s1 = atomicAdd(&g_counts[i1], 1);
            int s2 = atomicAdd(&g_counts[i2], 1);
            g_tok_e[2 * t] = i1;     g_tok_e[2 * t + 1] = i2;
            g_tok_slot[2 * t] = s1;  g_tok_slot[2 * t + 1] = s2;
            g_tok_w[2 * t] = w1;     g_tok_w[2 * t + 1] = w2;
        }
        __syncthreads();
    }
}

// ---------------- launch 3: fused scatter+gather + zero out ----------------
__global__ void sg_kernel(const float* __restrict__ residual, float* __restrict__ out) {
    int i = blockIdx.x;                 // 8192 blocks
    int tid = threadIdx.x;              // 128
    if (i == 0 && tid == 0) {
        int tile = 0;
        #pragma unroll
        for (int e = 0; e < NEXP; e++) {
            int nt = (g_counts[e] + 127) >> 7;
            for (int k = 0; k < nt; k++) g_tile_expert[tile++] = e;
        }
        for (; tile < MAX_TILES; tile++) g_tile_expert[tile] = -1;
    }
    reinterpret_cast<uint4*>(out)[(size_t)i * 128 + tid] = make_uint4(0, 0, 0, 0);

    int e = g_tok_e[i];
    int off = 0;
    #pragma unroll
    for (int q = 0; q < NEXP; q++)
        if (q < e) off += ((g_counts[q] + 127) >> 7) << 7;
    int row = off + g_tok_slot[i];
    int tok = i >> 1;
    if (tid == 0) {
        g_row_tok[row] = tok;
        g_row_w[row] = g_tok_w[i];
    }
    int c = tid * 8;
    const float4* src = reinterpret_cast<const float4*>(residual + (size_t)tok * DDIM + c);
    float4 a = src[0], b = src[1];
    __half2 h[4];
    h[0] = __floats2half2_rn(a.x, a.y); h[1] = __floats2half2_rn(a.z, a.w);
    h[2] = __floats2half2_rn(b.x, b.y); h[3] = __floats2half2_rn(b.z, b.w);
    int rt = row >> 7, m = row & 127;
    int kt = c >> 6, k = c & 63;
    reinterpret_cast<uint4*>(g_X)[(size_t)(rt * 16 + kt) * 1024 + m * 8 + ((k >> 3) ^ (m & 7))] =
        *reinterpret_cast<uint4*>(h);
}

// ================= launch 4 (PROFILED): GEMM1, 512 thr, 4x4 warps 32x32, 4-stage =================
#define G1_STG 4
#define G1_NC 16
#define G1_STAGE_B 49152
#define G1_SMEM (1024 + G1_STG * G1_STAGE_B)
#define G1_WARPS 16

__global__ void __launch_bounds__(512, 1) gemm1_kernel(const float* __restrict__ bg,
                                                       const float* __restrict__ bu) {
    int e = g_tile_expert[blockIdx.y];
    if (e < 0) return;
    int rt = blockIdx.y, nt_ = blockIdx.x;
    int n0 = nt_ * 128;
    extern __shared__ char smc[];
    uint32_t sb = smem_u32(smc);
    int tid = threadIdx.x, lane = tid & 31, w = tid >> 5;
    int wm = w >> 2, wn = w & 3;        // 4x4 warps, 32x32 each

    const char* Ablk  = (const char*)g_X  + (size_t)(rt * 16) * 16384;
    const char* Bgblk = (const char*)g_Wg + (size_t)((e * 16 + nt_) * 16) * 16384;
    const char* Bublk = (const char*)g_Wu + (size_t)((e * 16 + nt_) * 16) * 16384;

    if (tid == 0) {
        #pragma unroll
        for (int s = 0; s < G1_STG; s++) {
            mbar_init(sb + 8 * s, 1);                 // full
            mbar_init(sb + 64 + 8 * s, G1_WARPS);     // empty
        }
    }
    __syncthreads();
    FENCE_ASYNC();

    auto issue = [&](int c) {
        int b = c % G1_STG;
        uint32_t mb = sb + 8 * b;
        uint32_t dst = sb + 1024 + b * G1_STAGE_B;
        mbar_expect_tx(mb, G1_STAGE_B);
        bulk_g2s(dst,          Ablk  + (size_t)c * 16384, 16384, mb);
        bulk_g2s(dst + 16384,  Bgblk + (size_t)c * 16384, 16384, mb);
        bulk_g2s(dst + 32768,  Bublk + (size_t)c * 16384, 16384, mb);
    };
    if (tid == 0) { issue(0); issue(1); issue(2); issue(3); }

    float accG[2][4][4], accU[2][4][4];
    #pragma unroll
    for (int mt = 0; mt < 2; mt++)
        #pragma unroll
        for (int nt = 0; nt < 4; nt++)
            #pragma unroll
            for (int q = 0; q < 4; q++) { accG[mt][nt][q] = 0.f; accU[mt][nt][q] = 0.f; }

    for (int c = 0; c < G1_NC; c++) {
        int b = c % G1_STG;
        uint32_t ph = (c / G1_STG) & 1;
        mbar_wait(sb + 8 * b, ph);
        uint32_t Ab = sb + 1024 + b * G1_STAGE_B;
        uint32_t Bgb = Ab + 16384, Bub = Ab + 32768;
        #pragma unroll
        for (int kk = 0; kk < 64; kk += 16) {
            uint32_t a[2][4];
            #pragma unroll
            for (int mt = 0; mt < 2; mt++) {
                int m = wm * 32 + mt * 16 + (lane & 15);
                int colk = kk + (lane >> 4) * 8;
                ldm_x4(a[mt], Ab + m * 128 + ((colk * 2) ^ ((m & 7) << 4)));
            }
            uint32_t bG[2][4], bU[2][4];
            #pragma unroll
            for (int p = 0; p < 2; p++) {
                int krow = kk + (lane & 15);
                int coln = wn * 32 + p * 16 + (lane >> 4) * 8;
                uint32_t off = krow * 256 + ((coln * 2) ^ ((krow & 7) << 4));
                ldm_x4_t(bG[p], Bgb + off);
                ldm_x4_t(bU[p], Bub + off);
            }
            #pragma unroll
            for (int mt = 0; mt < 2; mt++)
                #pragma unroll
                for (int nt = 0; nt < 4; nt++) {
                    mma16816(accG[mt][nt], a[mt], &bG[nt >> 1][(nt & 1) * 2]);
                    mma16816(accU[mt][nt], a[mt], &bU[nt >> 1][(nt & 1) * 2]);
                }
        }
        __syncwarp();
        if (lane == 0) mbar_arrive(sb + 64 + 8 * b);
        int cn = c + G1_STG;
        if (cn < G1_NC && w == (c & (G1_WARPS - 1)) && lane == 0) {
            mbar_wait(sb + 64 + 8 * b, ph);
            issue(cn);
        }
    }

    // epilogue: h = silu(g+bg)*(u+bu) -> fp16 H in A-block layout
    const float* bgp = bg + e * MDIM + n0 + wn * 32;
    const float* bup = bu + e * MDIM + n0 + wn * 32;
    #pragma unroll
    for (int nt = 0; nt < 4; nt++) {
        int colb = nt * 8 + (lane & 3) * 2;
        float b_g0 = bgp[colb], b_g1 = bgp[colb + 1];
        float b_u0 = bup[colb], b_u1 = bup[colb + 1];
        int col = n0 + wn * 32 + colb;
        int kt = col >> 6, k2 = (col & 63) * 2;
        size_t blk = (size_t)(rt * 32 + kt) * 16384;
        #pragma unroll
        for (int mt = 0; mt < 2; mt++) {
            int m = wm * 32 + mt * 16 + (lane >> 2);
            float g0 = accG[mt][nt][0] + b_g0, g1 = accG[mt][nt][1] + b_g1;
            float u0 = accU[mt][nt][0] + b_u0, u1 = accU[mt][nt][1] + b_u1;
            float h0 = g0 / (1.f + __expf(-g0)) * u0;
            float h1 = g1 / (1.f + __expf(-g1)) * u1;
            *reinterpret_cast<__half2*>((char*)g_H + blk + m * 128 + (k2 ^ ((m & 7) << 4))) =
                __floats2half2_rn(h0, h1);
            int m2 = m + 8;
            float g2 = accG[mt][nt][2] + b_g0, g3 = accG[mt][nt][3] + b_g1;
            float u2 = accU[mt][nt][2] + b_u0, u3 = accU[mt][nt][3] + b_u1;
            float h2 = g2 / (1.f + __expf(-g2)) * u2;
            float h3 = g3 / (1.f + __expf(-g3)) * u3;
            *reinterpret_cast<__half2*>((char*)g_H + blk + m2 * 128 + (k2 ^ ((m2 & 7) << 4))) =
                __floats2half2_rn(h2, h3);
        }
    }
}

// ================= launch 6: GEMM2 + fused combine (atomic 2-term add), 2 CTAs/SM =================
#define G2_STG 3
#define G2_NC 32
#define G2_STAGE_B 32768
#define G2_SMEM (1024 + G2_STG * G2_STAGE_B)
#define G2_WARPS 8

__global__ void __launch_bounds__(256, 2) gemm2_kernel(float* __restrict__ out,
                                                       const float* __restrict__ bo) {
    int e = g_tile_expert[blockIdx.y];
    if (e < 0) return;
    int rt = blockIdx.y, nt_ = blockIdx.x;
    int row0 = rt * 128, n0 = nt_ * 128;
    extern __shared__ char smc[];
    uint32_t sb = smem_u32(smc);
    int tid = threadIdx.x, lane = tid & 31, w = tid >> 5;
    int wm = w >> 2, wn = w & 3;

    const char* Ablk = (const char*)g_H  + (size_t)(rt * 32) * 16384;
    const char* Bblk = (const char*)g_Wo + (size_t)((e * 8 + nt_) * 32) * 16384;

    if (tid == 0) {
        #pragma unroll
        for (int s = 0; s < G2_STG; s++) {
            mbar_init(sb + 8 * s, 1);
            mbar_init(sb + 64 + 8 * s, G2_WARPS);
        }
    }
    __syncthreads();
    FENCE_ASYNC();

    auto issue = [&](int c) {
        int b = c % G2_STG;
        uint32_t mb = sb + 8 * b;
        uint32_t dst = sb + 1024 + b * G2_STAGE_B;
        mbar_expect_tx(mb, G2_STAGE_B);
        bulk_g2s(dst,         Ablk + (size_t)c * 16384, 16384, mb);
        bulk_g2s(dst + 16384, Bblk + (size_t)c * 16384, 16384, mb);
    };
    if (tid == 0) { issue(0); issue(1); issue(2); }

    float acc[4][4][4];
    #pragma unroll
    for (int mt = 0; mt < 4; mt++)
        #pragma unroll
        for (int nt = 0; nt < 4; nt++)
            #pragma unroll
            for (int q = 0; q < 4; q++) acc[mt][nt][q] = 0.f;

    for (int c = 0; c < G2_NC; c++) {
        int b = c % G2_STG;
        uint32_t ph = (c / G2_STG) & 1;
        mbar_wait(sb + 8 * b, ph);
        uint32_t Ab = sb + 1024 + b * G2_STAGE_B;
        uint32_t Bb = Ab + 16384;
        #pragma unroll
        for (int kk = 0; kk < 64; kk += 16) {
            uint32_t a[4][4];
            #pragma unroll
            for (int mt = 0; mt < 4; mt++) {
                int m = wm * 64 + mt * 16 + (lane & 15);
                int colk = kk + (lane >> 4) * 8;
                ldm_x4(a[mt], Ab + m * 128 + ((colk * 2) ^ ((m & 7) << 4)));
            }
            uint32_t bB[2][4];
            #pragma unroll
            for (int p = 0; p < 2; p++) {
                int krow = kk + (lane & 15);
                int coln = wn * 32 + p * 16 + (lane >> 4) * 8;
                ldm_x4_t(bB[p], Bb + krow * 256 + ((coln * 2) ^ ((krow & 7) << 4)));
            }
            #pragma unroll
            for (int mt = 0; mt < 4; mt++)
                #pragma unroll
                for (int nt = 0; nt < 4; nt++)
                    mma16816(acc[mt][nt], a[mt], &bB[nt >> 1][(nt & 1) * 2]);
        }
        __syncwarp();
        if (lane == 0) mbar_arrive(sb + 64 + 8 * b);
        int cn = c + G2_STG;
        if (cn < G2_NC && w == (c & (G2_WARPS - 1)) && lane == 0) {
            mbar_wait(sb + 64 + 8 * b, ph);
            issue(cn);
        }
    }

    // epilogue: fused combine -- out[tok] += w * (acc + bo[e])
    const float* bop = bo + e * DDIM;
    #pragma unroll
    for (int mt = 0; mt < 4; mt++) {
        int row = row0 + wm * 64 + mt * 16 + (lane >> 2);
        int tok0 = g_row_tok[row];
        float w0 = g_row_w[row];
        int tok1 = g_row_tok[row + 8];
        float w1 = g_row_w[row + 8];
        #pragma unroll
        for (int nt = 0; nt < 4; nt++) {
            int col = n0 + wn * 32 + nt * 8 + (lane & 3) * 2;
            float b0 = bop[col], b1 = bop[col + 1];
            if (tok0 >= 0) {
                float* dst = out + (size_t)tok0 * DDIM + col;
                atomicAdd(dst,     w0 * (acc[mt][nt][0] + b0));
                atomicAdd(dst + 1, w0 * (acc[mt][nt][1] + b1));
            }
            if (tok1 >= 0) {
                float* dst = out + (size_t)tok1 * DDIM + col;
                atomicAdd(dst,     w1 * (acc[mt][nt][2] + b0));
                atomicAdd(dst + 1, w1 * (acc[mt][nt][3] + b1));
            }
        }
    }
}

// ---------------- launch: fork convert_o onto side stream, hidden under GEMM1 ----------------
extern "C" void kernel_launch(void* const* d_in, const int* in_sizes, int n_in,
                              void* d_out, int out_size) {
    const float* residual = (const float*)d_in[0];
    const float* Wr = (const float*)d_in[1];
    const float* Wg = (const float*)d_in[2];
    const float* bg = (const float*)d_in[3];
    const float* Wu = (const float*)d_in[4];
    const float* bu = (const float*)d_in[5];
    const float* Wo = (const float*)d_in[6];
    const float* bo = (const float*)d_in[7];
    float* out = (float*)d_out;

    static cudaStream_t s2 = nullptr;
    static cudaEvent_t ev_sg = nullptr, ev_o = nullptr;
    if (!s2) {
        cudaStreamCreateWithFlags(&s2, cudaStreamNonBlocking);
        cudaEventCreateWithFlags(&ev_sg, cudaEventDisableTiming);
        cudaEventCreateWithFlags(&ev_o, cudaEventDisableTiming);
        cudaFuncSetAttribute(gemm1_kernel, cudaFuncAttributeMaxDynamicSharedMemorySize, G1_SMEM);
        cudaFuncSetAttribute(gemm2_kernel, cudaFuncAttributeMaxDynamicSharedMemorySize, G2_SMEM);
    }

    dim3 cg(2048, 2);
    convert_gu_kernel<<<cg, 256>>>(Wg, Wu);                  // 1
    router_kernel<<<T_TOKENS / RT_TPB, 256>>>(residual, Wr); // 2
    sg_kernel<<<T_TOKENS * 2, 128>>>(residual, out);         // 3
    cudaEventRecord(ev_sg, 0);
    dim3 g1(MDIM / 128, MAX_TILES);
    gemm1_kernel<<<g1, 512, G1_SMEM>>>(bg, bu);              // 4 <-- profiled
    cudaStreamWaitEvent(s2, ev_sg, 0);                       // side: run during gemm1
    convert_o_kernel<<<2048, 256, 0, s2>>>(Wo);              // 5 (side stream)
    cudaEventRecord(ev_o, s2);
    cudaStreamWaitEvent(0, ev_o, 0);
    dim3 g2(DDIM / 128, MAX_TILES);
    gemm2_kernel<<<g2, 256, G2_SMEM>>>(out, bo);             // 6 (fused combine)
}